// round 16
// baseline (speedup 1.0000x reference)
#include <cuda_runtime.h>
#include <cuda_fp16.h>
#include <cstdint>

#define BATCH   2048
#define IN_DIM  512
#define OUT_DIM 512
#define SDIM    8
#define KDIM    4096
#define ROWLEN  513

#define BM 128
#define BN 32
#define CHUNK 64
#define NTH 256                      // 2 s-groups x 4 warps

#define SROWB 144
#define A_BUF_BYTES (BM * SROWB)     // 18432 x3
#define OFF_A 0
#define OFF_BASIS (3 * A_BUF_BYTES)                // 55296
#define OFF_BW (OFF_BASIS + BM * SDIM * 4)         // 59392
#define SMEM_TOTAL (OFF_BW + SDIM * BN * 4)        // 60416
#define RED_STRIDE 34

// ---------------------------------------------------------------------------
__device__ __forceinline__ uint32_t smem_u32(const void* p) {
    uint32_t a;
    asm("{ .reg .u64 t; cvta.to.shared.u64 t, %1; cvt.u32.u64 %0, t; }"
        : "=r"(a) : "l"(p));
    return a;
}
__device__ __forceinline__ void cp16(uint32_t dst, const void* src) {
    asm volatile("cp.async.cg.shared.global [%0], [%1], 16;"
                 :: "r"(dst), "l"(src) : "memory");
}
#define CP_COMMIT() asm volatile("cp.async.commit_group;" ::: "memory")
#define CP_WAIT(n)  asm volatile("cp.async.wait_group %0;" :: "n"(n) : "memory")

__device__ __forceinline__ void ldm_x4(uint32_t* r, uint32_t addr) {
    asm volatile("ldmatrix.sync.aligned.m8n8.x4.shared.b16 {%0,%1,%2,%3}, [%4];"
                 : "=r"(r[0]), "=r"(r[1]), "=r"(r[2]), "=r"(r[3]) : "r"(addr));
}
__device__ __forceinline__ void mma_f16(float* d, const uint32_t* a, const uint32_t* b) {
    asm volatile(
        "mma.sync.aligned.m16n8k16.row.col.f32.f16.f16.f32 "
        "{%0,%1,%2,%3}, {%4,%5,%6,%7}, {%8,%9}, {%0,%1,%2,%3};"
        : "+f"(d[0]), "+f"(d[1]), "+f"(d[2]), "+f"(d[3])
        : "r"(a[0]), "r"(a[1]), "r"(a[2]), "r"(a[3]), "r"(b[0]), "r"(b[1]));
}
__device__ __forceinline__ uint32_t hmul2u(uint32_t a, uint32_t b) {
    __half2 r = __hmul2(*(__half2*)&a, *(__half2*)&b);
    return *(uint32_t*)&r;
}

// ---------------------------------------------------------------------------
__device__ float g_basis[BATCH * SDIM];
__device__ __align__(16) __half g_F[BATCH * IN_DIM];
// B in mma fragment order: [nblk(16)][kstep(256)][half(2)][lane(32)][4 x u32]
__device__ __align__(16) __half g_Wfrag[OUT_DIM * KDIM];

// ---------------------------------------------------------------------------
// Merged prep (same as R12/R15): F fp16 + basis; W -> fragment layout.
// ---------------------------------------------------------------------------
__global__ void prep_kernel(const float* __restrict__ inputs,
                            const float* __restrict__ W) {
    const int bid = blockIdx.x;
    const int tid = threadIdx.x;
    if (bid < 256) {
        const int t0 = bid * 256 + tid;
#pragma unroll
        for (int j = 0; j < 8; ++j) {
            int g = t0 + j * 65536;
            int b = g >> 8, p = g & 255;
            const float* row = inputs + (size_t)b * ROWLEN;
            float x0 = __ldg(row + 1 + 2 * p);
            float x1 = __ldg(row + 2 + 2 * p);
            __half2 h = __floats2half2_rn(x0, x1);
            ((uint32_t*)g_F)[g] = *(uint32_t*)&h;
        }
        if (t0 < BATCH) {
            float tt = __ldg(&inputs[(size_t)t0 * ROWLEN]);
            float t2 = tt * tt, t3 = t2 * tt;
            float* dst = &g_basis[t0 * SDIM];
            dst[0] = 1.0f; dst[1] = tt; dst[2] = t2; dst[3] = t3;
            const float kn[4] = {0.2f, 0.4f, 0.6f, 0.8f};
#pragma unroll
            for (int j = 0; j < 4; ++j) {
                float u = fmaxf(tt - kn[j], 0.0f);
                dst[4 + j] = u * u * u;
            }
        }
    } else {
        const int wb   = bid - 256;                    // 0..1023
        const int lane = tid & 31;
        const int h    = (tid >> 5) & 1;
        const int ks   = (wb * 4 + (tid >> 6)) & 255;
        const int nblk = wb >> 6;
        const int n0 = nblk * 32 + h * 16 + (lane >> 2);
        const int k0 = ks * 16 + (lane & 3) * 2;
        const int s  = k0 >> 9;
        const int i  = k0 & 511;
        const float* Wb = W + ((size_t)s << 18);
        uint32_t v[4];
        {
            __half2 a = __floats2half2_rn(__ldg(&Wb[(size_t)i * 512 + n0]),
                                          __ldg(&Wb[(size_t)(i + 1) * 512 + n0]));
            __half2 b = __floats2half2_rn(__ldg(&Wb[(size_t)(i + 8) * 512 + n0]),
                                          __ldg(&Wb[(size_t)(i + 9) * 512 + n0]));
            __half2 c = __floats2half2_rn(__ldg(&Wb[(size_t)i * 512 + n0 + 8]),
                                          __ldg(&Wb[(size_t)(i + 1) * 512 + n0 + 8]));
            __half2 d = __floats2half2_rn(__ldg(&Wb[(size_t)(i + 8) * 512 + n0 + 8]),
                                          __ldg(&Wb[(size_t)(i + 9) * 512 + n0 + 8]));
            v[0] = *(uint32_t*)&a; v[1] = *(uint32_t*)&b;
            v[2] = *(uint32_t*)&c; v[3] = *(uint32_t*)&d;
        }
        ((uint4*)g_Wfrag)[(size_t)wb * 256 + tid] = *(uint4*)v;
    }
}

// ---------------------------------------------------------------------------
// GEMM: R15 structure + B prefetch distance 3 (full ring-4) + A triple buffer
// with CP_WAIT(1) (chunk boundary no longer drains the pipe). 2 CTAs/SM.
// ---------------------------------------------------------------------------
__global__ __launch_bounds__(NTH, 2)
void vclinear_mma_kernel(const float* __restrict__ bwts, float* __restrict__ out) {
    extern __shared__ char smem[];
    const uint32_t sb = smem_u32(smem);
    const int tid  = threadIdx.x;
    const int g    = tid >> 7;
    const int gwid = (tid >> 5) & 3;
    const int lane = tid & 31;
    const int block_n = blockIdx.x * BN;
    const int block_m = blockIdx.y * BM;

    float* sBasis = (float*)(smem + OFF_BASIS);
    float* sBw    = (float*)(smem + OFF_BW);
    for (int q = tid; q < BM * SDIM; q += NTH)
        sBasis[q] = g_basis[(block_m + (q >> 3)) * SDIM + (q & 7)];
    for (int q = tid; q < SDIM * BN; q += NTH)
        sBw[q] = bwts[(q >> 5) * OUT_DIM + block_n + (q & 31)];

    const int ca = tid & 7;
    const int ra = tid >> 3;

#define LOAD_A(chunk) do {                                                       \
    const uint32_t d = sb + OFF_A + ((chunk) % 3) * A_BUF_BYTES;                 \
    const size_t base = (size_t)block_m * IN_DIM + (chunk) * CHUNK + ca * 8;     \
    _Pragma("unroll")                                                            \
    for (int j = 0; j < 4; ++j) {                                                \
        int row = ra + j * 32;                                                   \
        cp16(d + row * SROWB + ca * 16, g_F + base + (size_t)row * IN_DIM);      \
    }                                                                            \
} while (0)

    const int m0 = gwid * 32;
    const uint32_t aoff = (m0 + (lane & 15)) * SROWB + (lane >> 4) * 16;

    const uint4* Bbase = (const uint4*)g_Wfrag + (size_t)blockIdx.x * 16384 + lane;

#define LDB(dst, kstep) do {                                                     \
    uint4 x = __ldg(Bbase + (kstep) * 64);                                       \
    uint4 y = __ldg(Bbase + (kstep) * 64 + 32);                                  \
    (dst)[0] = x.x; (dst)[1] = x.y; (dst)[2] = x.z; (dst)[3] = x.w;              \
    (dst)[4] = y.x; (dst)[5] = y.y; (dst)[6] = y.z; (dst)[7] = y.w;              \
} while (0)

    // kstep for pipeline position p: chunk=p>>4, s=g*4+((p&15)>>2), kk=p&3
#define KSIX(p) ((g * 4 + (((p) & 15) >> 2)) * 32 + ((p) >> 4) * 4 + ((p) & 3))

    uint32_t af[4][2][4];
    float acc[2][4][4];
#pragma unroll
    for (int i = 0; i < 2; ++i)
#pragma unroll
        for (int j = 0; j < 4; ++j)
#pragma unroll
            for (int r = 0; r < 4; ++r) acc[i][j][r] = 0.0f;

    // prologue: A chunks 0,1 in flight; B positions 0..2 resident (distance 3)
    LOAD_A(0);
    CP_COMMIT();
    LOAD_A(1);
    CP_COMMIT();
    uint32_t bq[4][8];
    LDB(bq[0], KSIX(0));
    LDB(bq[1], KSIX(1));
    LDB(bq[2], KSIX(2));
    __syncthreads();            // sBasis/sBw visible

    for (int chunk = 0; chunk < 8; ++chunk) {
        CP_WAIT(1);             // chunk's A ready; chunk+1 may still be in flight
        __syncthreads();
        if (chunk + 2 < 8) LOAD_A(chunk + 2);
        CP_COMMIT();

        // A tile -> registers for this chunk
        const uint32_t aB = sb + OFF_A + (chunk % 3) * A_BUF_BYTES;
#pragma unroll
        for (int kk = 0; kk < 4; ++kk)
#pragma unroll
            for (int ma = 0; ma < 2; ++ma)
                ldm_x4(af[kk][ma], aB + aoff + ma * 16 * SROWB + kk * 32);

#pragma unroll
        for (int it = 0; it < 4; ++it) {
            const int s = g * 4 + it;
            uint32_t hb[4];
#pragma unroll
            for (int i = 0; i < 4; ++i) {
                float bv = sBasis[(m0 + (lane >> 2) + 8 * i) * SDIM + s];
                __half2 h = __float2half2_rn(bv);
                hb[i] = *(uint32_t*)&h;
            }
#pragma unroll
            for (int kk = 0; kk < 4; ++kk) {
                const int p  = chunk * 16 + it * 4 + kk;
                const int pb = p & 3;
                const int pp = p + 3;                       // distance-3 prefetch
                if (pp < 128) LDB(bq[pp & 3], KSIX(pp));
#pragma unroll
                for (int ma = 0; ma < 2; ++ma) {
                    uint32_t at[4];
                    at[0] = hmul2u(af[kk][ma][0], hb[2 * ma]);
                    at[1] = hmul2u(af[kk][ma][1], hb[2 * ma + 1]);
                    at[2] = hmul2u(af[kk][ma][2], hb[2 * ma]);
                    at[3] = hmul2u(af[kk][ma][3], hb[2 * ma + 1]);
#pragma unroll
                    for (int na = 0; na < 4; ++na)
                        mma_f16(acc[ma][na], at, &bq[pb][na * 2]);
                }
            }
        }
    }

    // cross-group reduction: g1 stages partials, g0 adds + bias + store
    float* red = (float*)(smem + OFF_A);
    __syncthreads();
    if (g == 1) {
#pragma unroll
        for (int ma = 0; ma < 2; ++ma)
#pragma unroll
            for (int half = 0; half < 2; ++half) {
                const int row = m0 + ma * 16 + (lane >> 2) + half * 8;
#pragma unroll
                for (int na = 0; na < 4; ++na) {
                    const int col = na * 8 + 2 * (lane & 3);
                    *(float2*)&red[row * RED_STRIDE + col] =
                        make_float2(acc[ma][na][half * 2], acc[ma][na][half * 2 + 1]);
                }
            }
    }
    __syncthreads();
    if (g == 0) {
#pragma unroll
        for (int ma = 0; ma < 2; ++ma) {
#pragma unroll
            for (int half = 0; half < 2; ++half) {
                const int row = m0 + ma * 16 + (lane >> 2) + half * 8;
                float bsv[SDIM];
#pragma unroll
                for (int s = 0; s < SDIM; ++s) bsv[s] = sBasis[row * SDIM + s];
#pragma unroll
                for (int na = 0; na < 4; ++na) {
                    const int col = na * 8 + 2 * (lane & 3);
                    float b0r = 0.0f, b1r = 0.0f;
#pragma unroll
                    for (int s = 0; s < SDIM; ++s) {
                        b0r = fmaf(bsv[s], sBw[s * BN + col], b0r);
                        b1r = fmaf(bsv[s], sBw[s * BN + col + 1], b1r);
                    }
                    float2 o = *(float2*)&red[row * RED_STRIDE + col];
                    float2 v;
                    v.x = acc[ma][na][half * 2 + 0] + o.x + b0r;
                    v.y = acc[ma][na][half * 2 + 1] + o.y + b1r;
                    *(float2*)&out[(size_t)(block_m + row) * OUT_DIM + block_n + col] = v;
                }
            }
        }
    }
}

// ---------------------------------------------------------------------------
extern "C" void kernel_launch(void* const* d_in, const int* in_sizes, int n_in,
                              void* d_out, int out_size) {
    const float* inputs = (const float*)d_in[0];
    const float* W      = (const float*)d_in[1];
    const float* bwts   = (const float*)d_in[2];
    float* out          = (float*)d_out;

    cudaFuncSetAttribute(vclinear_mma_kernel,
                         cudaFuncAttributeMaxDynamicSharedMemorySize, SMEM_TOTAL);

    prep_kernel<<<1280, 256>>>(inputs, W);

    dim3 grid(OUT_DIM / BN, BATCH / BM);   // (16, 16) = 256 CTAs, 2/SM
    vclinear_mma_kernel<<<grid, NTH, SMEM_TOTAL>>>(bwts, out);
}